// round 12
// baseline (speedup 1.0000x reference)
#include <cuda_runtime.h>
#include <cuda_bf16.h>
#include <cstdint>

#define NB 16
#define NE 2048
#define NP 16384
#define NL 5
#define ND 64

#define CSZ 8               // cluster size (CTAs per batch)
#define ESL (NE / CSZ)      // 256 edges per CTA slice
#define ETH 1024            // threads per CTA
#define PBLK (NP / CSZ)     // 2048 paths per CTA
#define EPPT (PBLK / ETH)   // 2 paths per thread

// ---------------------------------------------------------------------------
// ONE fused kernel. Cluster of 8 CTAs = one batch. grid (8,16) = 128 CTAs,
// 16 clusters, single wave.
//   Phase A: path index loads -> registers (latency hides under B)
//   Phase B: each CTA computes dot-table slice for edges [rank*256,(rank+1)*256)
//            into its own smem (5 KB). Total chip FMA = 10.5M (~0.6us), emb
//            read exactly once.
//   barrier.cluster (publishes slices)
//   Phase C: gather dot[idx,l] from peer CTA (rank = idx>>8) via
//            mapa + ld.shared::cluster; reduce; store.
//   barrier.cluster (no CTA exits while peers still read its smem)
// ---------------------------------------------------------------------------
__global__ void __launch_bounds__(ETH) __cluster_dims__(CSZ, 1, 1)
fused_kernel(const float* __restrict__ emb, const void* __restrict__ paths,
             const float* __restrict__ ev, float* __restrict__ out)
{
    __shared__ float tab[ESL * NL];   // 5120 B slice of the dot table
    __shared__ float recip[8];
    __shared__ int s_is64;

    const int tid  = threadIdx.x;
    const int rank = blockIdx.x;      // cluster spans gridDim.x -> rank == x
    const int b    = blockIdx.y;

    // --- dtype sniff (every CTA samples the SAME 1024 odd words -> same verdict)
    {
        int bad = 0;
        if (tid < 256) {
            const int* pw = (const int*)paths;
            #pragma unroll 4
            for (int i = tid; i < 1024; i += 256) {
                int w = __ldg(pw + 2 * i + 1);
                bad |= (w != 0 && w != -1);   // int64 sign-ext words are 0/-1
            }
        }
        bad = __syncthreads_or(bad);
        if (tid == 0) s_is64 = bad ? 0 : 1;
        if (tid < 8)  recip[tid] = (tid >= 1 && tid <= 5)
                                 ? 1.0f / ((float)tid + 1e-9f) : 0.f;
        __syncthreads();
    }
    const bool is64 = (s_is64 != 0);

    // --- Phase A: path index loads into registers (10 independent LDGs) ---
    // Low 32-bit word suffices for both dtypes (low word of -1 is -1; ids < 2^31).
    const int p0 = rank * PBLK;
    int w[EPPT][NL];
    if (is64) {
        const int2* src = reinterpret_cast<const int2*>(
            (const unsigned char*)paths + ((size_t)b * NP + p0) * NL * 8);
        #pragma unroll
        for (int it = 0; it < EPPT; it++) {
            const int2* q = src + (it * ETH + tid) * NL;
            #pragma unroll
            for (int l = 0; l < NL; l++) w[it][l] = __ldg(q + l).x;
        }
    } else {
        const int* src = reinterpret_cast<const int*>(paths)
                       + ((size_t)b * NP + p0) * NL;
        #pragma unroll
        for (int it = 0; it < EPPT; it++) {
            const int* q = src + (it * ETH + tid) * NL;
            #pragma unroll
            for (int l = 0; l < NL; l++) w[it][l] = __ldg(q + l);
        }
    }

    // --- Phase B: dot-table slice. 8 lanes per edge row, 4 rows per warp,
    //     32 warps x 4 = 128 rows per pass, 2 passes for 256 rows. ---
    {
        const int warp = tid >> 5;
        const int lane = tid & 31;
        const int grp  = lane >> 3;      // row within warp's group of 4
        const int sub  = lane & 7;       // 8 lanes per row
        const float4* ev4 = reinterpret_cast<const float4*>(ev);

        #pragma unroll
        for (int pass = 0; pass < 2; pass++) {
            const int el = pass * 128 + warp * 4 + grp;   // local edge 0..255
            const int e  = rank * ESL + el;
            const float4* rp = reinterpret_cast<const float4*>(emb)
                             + ((size_t)b * NE + e) * (ND / 4);
            float4 v0 = rp[sub];
            float4 v1 = rp[sub + 8];
            float res = 0.f;
            #pragma unroll
            for (int l = 0; l < NL; l++) {
                float4 e0 = ev4[l * (ND / 4) + sub];
                float4 e1 = ev4[l * (ND / 4) + 8 + sub];
                float s = v0.x * e0.x + v0.y * e0.y + v0.z * e0.z + v0.w * e0.w
                        + v1.x * e1.x + v1.y * e1.y + v1.z * e1.z + v1.w * e1.w;
                s += __shfl_xor_sync(0xffffffffu, s, 1);
                s += __shfl_xor_sync(0xffffffffu, s, 2);
                s += __shfl_xor_sync(0xffffffffu, s, 4);
                if (sub == l) res = s;
            }
            if (sub < NL) tab[el * NL + sub] = res;
        }
    }

    // publish slices across the cluster (release) and wait for peers
    asm volatile("barrier.cluster.arrive.aligned;" ::: "memory");
    asm volatile("barrier.cluster.wait.aligned;"   ::: "memory");

    // --- Phase C: gather from peer slices via DSMEM ---
    {
        const uint32_t tab_base =
            (uint32_t)__cvta_generic_to_shared(tab);

        #pragma unroll
        for (int it = 0; it < EPPT; it++) {
            float acc = 0.f;
            int cnt = 0;
            #pragma unroll
            for (int l = 0; l < NL; l++) {
                const int idx = w[it][l];
                float v = 0.f;
                if (idx >= 0) {
                    const uint32_t r  = (uint32_t)idx >> 8;    // peer rank
                    const uint32_t el = (uint32_t)idx & (ESL - 1);
                    const uint32_t la = tab_base + ((el * NL + l) << 2);
                    uint32_t ra;
                    asm("mapa.shared::cluster.u32 %0, %1, %2;"
                        : "=r"(ra) : "r"(la), "r"(r));
                    asm("ld.shared::cluster.f32 %0, [%1];"
                        : "=f"(v) : "r"(ra));
                    cnt++;
                }
                acc += v;
            }
            out[(size_t)b * NP + p0 + it * ETH + tid] = acc * recip[cnt];
        }
    }

    // no CTA may exit while peers can still read its smem
    asm volatile("barrier.cluster.arrive.aligned;" ::: "memory");
    asm volatile("barrier.cluster.wait.aligned;"   ::: "memory");
}

// ---------------------------------------------------------------------------
extern "C" void kernel_launch(void* const* d_in, const int* in_sizes, int n_in,
                              void* d_out, int out_size) {
    const float* emb   = (const float*)d_in[0];  // (B, E, D) float32
    const void*  paths = d_in[1];                // (B, P, L) int64 or int32
    const float* ev    = (const float*)d_in[2];  // (L, D) float32
    float* out = (float*)d_out;                  // (B, P) float32

    dim3 grid(CSZ, NB);                          // (8, 16) = 128 CTAs, 16 clusters
    fused_kernel<<<grid, ETH>>>(emb, paths, ev, out);
}

// round 13
// speedup vs baseline: 1.7779x; 1.7779x over previous
#include <cuda_runtime.h>
#include <cuda_bf16.h>
#include <cstdint>

#define NB 16
#define NE 2048
#define NP 16384
#define NL 5
#define ND 64

#define CSZ 8               // cluster size (CTAs per batch)
#define ESL (NE / CSZ)      // 256 edges per CTA slice
#define ETH 1024            // threads per CTA
#define PBLK (NP / CSZ)     // 2048 paths per CTA
#define EPPT (PBLK / ETH)   // 2 paths per thread

// Exchange buffer for dot slices: [b][e][l]
__device__ __align__(16) float g_dot[NB * NE * NL];

// smem: 40 KB table + 40 KB compact path words + recip
#define SMEM_TAB_BYTES   (NE * NL * 4)          // 40960
#define SMEM_PATH_BYTES  (PBLK * NL * 4)        // 40960
#define FUSED_SMEM       (SMEM_TAB_BYTES + SMEM_PATH_BYTES + 64)

// ---------------------------------------------------------------------------
// ONE fused kernel. Cluster of 8 CTAs = one batch. grid (8,16), single wave.
//  A: stage this CTA's 2048 paths into smem, coalesced, low-32-bit words only
//     (valid for int64 and int32: low word of -1 is -1; ids < 2^31).
//  B: compute dot slice for edges [rank*256,(rank+1)*256) -> global g_dot.
//     threadfence + barrier.cluster publishes slices (release/acquire).
//  B2: read the FULL 40 KB batch table from L2 into local smem.
//  C: local LDS gather (addr = p*5+l, gcd(5,32)=1 -> conflict-light) + store.
// ---------------------------------------------------------------------------
__global__ void __launch_bounds__(ETH) __cluster_dims__(CSZ, 1, 1)
fused_kernel(const float* __restrict__ emb, const void* __restrict__ paths,
             const float* __restrict__ ev, float* __restrict__ out)
{
    extern __shared__ unsigned char smem[];
    float* tab   = reinterpret_cast<float*>(smem);                    // NE*NL
    int*   sp    = reinterpret_cast<int*>(smem + SMEM_TAB_BYTES);     // PBLK*NL
    float* recip = reinterpret_cast<float*>(smem + SMEM_TAB_BYTES + SMEM_PATH_BYTES);
    __shared__ int s_is64;

    const int tid  = threadIdx.x;
    const int rank = blockIdx.x;      // cluster spans x -> rank == blockIdx.x
    const int b    = blockIdx.y;

    // --- dtype sniff: every CTA samples the SAME 1024 odd words -> same verdict
    {
        int bad = 0;
        if (tid < 256) {
            const int* pw = (const int*)paths;
            #pragma unroll 4
            for (int i = tid; i < 1024; i += 256) {
                int w = __ldg(pw + 2 * i + 1);
                bad |= (w != 0 && w != -1);   // int64 sign-ext words are 0/-1
            }
        }
        bad = __syncthreads_or(bad);
        if (tid == 0) s_is64 = bad ? 0 : 1;
        if (tid < 8)  recip[tid] = (tid >= 1 && tid <= 5)
                                 ? 1.0f / ((float)tid + 1e-9f) : 0.f;  // cnt=0 -> 0
        __syncthreads();
    }
    const bool is64 = (s_is64 != 0);

    // --- Phase A: stage paths into smem, fully coalesced int4, compacted ---
    if (is64) {
        const int4* psrc = reinterpret_cast<const int4*>(
            (const unsigned char*)paths + ((size_t)b * NP + rank * PBLK) * NL * 8);
        int2* pdst = reinterpret_cast<int2*>(sp);
        #pragma unroll
        for (int i = tid; i < PBLK * NL / 2; i += ETH) {   // 5120 int4, 5/thread
            int4 v = __ldg(psrc + i);
            pdst[i] = make_int2(v.x, v.z);
        }
    } else {
        const int4* psrc = reinterpret_cast<const int4*>(
            (const unsigned char*)paths + ((size_t)b * NP + rank * PBLK) * NL * 4);
        int4* pdst = reinterpret_cast<int4*>(sp);
        #pragma unroll
        for (int i = tid; i < PBLK * NL / 4; i += ETH)     // 2560 int4, 2.5/thread
            pdst[i] = __ldg(psrc + i);
    }
    // (no sync yet — consumed after the __syncthreads in B2)

    // --- Phase B: dot slice -> global. 8 lanes/row, 4 rows/warp, 2 passes ---
    {
        const int warp = tid >> 5;
        const int lane = tid & 31;
        const int grp  = lane >> 3;
        const int sub  = lane & 7;
        const float4* ev4 = reinterpret_cast<const float4*>(ev);

        #pragma unroll
        for (int pass = 0; pass < 2; pass++) {
            const int e = rank * ESL + pass * 128 + warp * 4 + grp;  // edge id
            const float4* rp = reinterpret_cast<const float4*>(emb)
                             + ((size_t)b * NE + e) * (ND / 4);
            float4 v0 = rp[sub];
            float4 v1 = rp[sub + 8];
            float res = 0.f;
            #pragma unroll
            for (int l = 0; l < NL; l++) {
                float4 e0 = ev4[l * (ND / 4) + sub];
                float4 e1 = ev4[l * (ND / 4) + 8 + sub];
                float s = v0.x * e0.x + v0.y * e0.y + v0.z * e0.z + v0.w * e0.w
                        + v1.x * e1.x + v1.y * e1.y + v1.z * e1.z + v1.w * e1.w;
                s += __shfl_xor_sync(0xffffffffu, s, 1);
                s += __shfl_xor_sync(0xffffffffu, s, 2);
                s += __shfl_xor_sync(0xffffffffu, s, 4);
                if (sub == l) res = s;
            }
            if (sub < NL) g_dot[((size_t)b * NE + e) * NL + sub] = res;
        }
    }

    // publish slices cluster-wide: gpu-scope fence + cluster barrier
    __threadfence();
    asm volatile("barrier.cluster.arrive.aligned;" ::: "memory");
    asm volatile("barrier.cluster.wait.aligned;"   ::: "memory");

    // --- Phase B2: pull the full batch table from L2 into local smem ---
    {
        const float4* src4 = reinterpret_cast<const float4*>(g_dot + (size_t)b * NE * NL);
        float4* dst4 = reinterpret_cast<float4*>(tab);
        #pragma unroll
        for (int i = tid; i < (NE * NL) / 4; i += ETH)     // 2560 float4
            dst4[i] = __ldg(src4 + i);
    }
    __syncthreads();   // covers tab AND the Phase-A path staging

    // --- Phase C: local gather + reduce + coalesced store ---
    #pragma unroll
    for (int it = 0; it < EPPT; it++) {
        const int lp = it * ETH + tid;          // local p in [0, PBLK)
        const int* q = sp + lp * NL;
        float acc = 0.f;
        int cnt = 0;
        #pragma unroll
        for (int l = 0; l < NL; l++) {
            int idx = q[l];
            if (idx >= 0) { acc += tab[idx * NL + l]; cnt++; }
        }
        out[(size_t)b * NP + rank * PBLK + lp] = acc * recip[cnt];
    }
}

// ---------------------------------------------------------------------------
extern "C" void kernel_launch(void* const* d_in, const int* in_sizes, int n_in,
                              void* d_out, int out_size) {
    const float* emb   = (const float*)d_in[0];  // (B, E, D) float32
    const void*  paths = d_in[1];                // (B, P, L) int64 or int32
    const float* ev    = (const float*)d_in[2];  // (L, D) float32
    float* out = (float*)d_out;                  // (B, P) float32

    cudaFuncSetAttribute(fused_kernel, cudaFuncAttributeMaxDynamicSharedMemorySize,
                         FUSED_SMEM);
    dim3 grid(CSZ, NB);                          // (8, 16) = 128 CTAs, 16 clusters
    fused_kernel<<<grid, ETH, FUSED_SMEM>>>(emb, paths, ev, out);
}

// round 15
// speedup vs baseline: 3.1844x; 1.7911x over previous
#include <cuda_runtime.h>
#include <cuda_bf16.h>
#include <cstdint>

#define NB 16
#define NE 2048
#define NP 16384
#define NL 5
#define ND 64

#define CSZ 8               // cluster size (CTAs per batch)
#define ESL (NE / CSZ)      // 256 edges per CTA slice
#define ETH 1024            // threads per CTA
#define PBLK (NP / CSZ)     // 2048 paths per CTA
#define EPPT (PBLK / ETH)   // 2 paths per thread

// Exchange buffer for dot slices: [b][e][l]
__device__ __align__(16) float g_dot[NB * NE * NL];

#define SMEM_TAB_BYTES   (NE * NL * 4)          // 40960
#define SMEM_PATH_BYTES  (PBLK * NL * 4)        // 40960
#define FUSED_SMEM       (SMEM_TAB_BYTES + SMEM_PATH_BYTES + 64)

// ---------------------------------------------------------------------------
// ONE fused kernel. Cluster of 8 CTAs = one batch. grid (8,16), single wave.
//  sniff:  1 warp, 256 samples -> s_is64
//  B:      dot slice for edges [rank*256,(rank+1)*256) -> g_dot (STG, no fence)
//  arrive: cluster release (publishes g_dot writes, non-blocking)
//  A:      stage this CTA's 2048 paths into smem (DRAM latency overlaps
//          peer skew + barrier), compact low-32-bit words
//  wait:   cluster acquire (L1 invalidated by CCTL.IVALL; g_dot visible)
//  B2:     pull full 40 KB batch table from L2 -> smem
//  C:      local LDS gather (addr = p*5+l, gcd(5,32)=1) + coalesced store
// ---------------------------------------------------------------------------
__global__ void __launch_bounds__(ETH) __cluster_dims__(CSZ, 1, 1)
fused_kernel(const float* __restrict__ emb, const void* __restrict__ paths,
             const float* __restrict__ ev, float* __restrict__ out)
{
    extern __shared__ unsigned char smem[];
    float* tab   = reinterpret_cast<float*>(smem);                    // NE*NL
    int*   sp    = reinterpret_cast<int*>(smem + SMEM_TAB_BYTES);     // PBLK*NL
    float* recip = reinterpret_cast<float*>(smem + SMEM_TAB_BYTES + SMEM_PATH_BYTES);
    __shared__ int s_is64;

    const int tid  = threadIdx.x;
    const int rank = blockIdx.x;      // cluster spans x -> rank == blockIdx.x
    const int b    = blockIdx.y;

    // --- dtype sniff: warp 0, 256 samples of odd 32-bit words.
    // int64 -> sign-extension words are 0/-1; P(int32 mimics) = (2/2049)^256.
    if (tid < 32) {
        const int* pw = (const int*)paths;
        int bad = 0;
        #pragma unroll
        for (int k = 0; k < 8; k++) {
            int w = __ldg(pw + 2 * (k * 32 + tid) + 1);
            bad |= (w != 0 && w != -1);
        }
        bad = __any_sync(0xffffffffu, bad);
        if (tid == 0) s_is64 = bad ? 0 : 1;
    }
    if (tid < 8) recip[tid] = (tid >= 1 && tid <= 5)
                            ? 1.0f / ((float)tid + 1e-9f) : 0.f;  // cnt=0 -> 0

    // --- Phase B: dot slice -> g_dot. 8 lanes/row, 4 rows/warp, 2 passes ---
    {
        const int warp = tid >> 5;
        const int lane = tid & 31;
        const int grp  = lane >> 3;
        const int sub  = lane & 7;
        const float4* ev4 = reinterpret_cast<const float4*>(ev);

        #pragma unroll
        for (int pass = 0; pass < 2; pass++) {
            const int e = rank * ESL + pass * 128 + warp * 4 + grp;  // edge id
            const float4* rp = reinterpret_cast<const float4*>(emb)
                             + ((size_t)b * NE + e) * (ND / 4);
            float4 v0 = rp[sub];
            float4 v1 = rp[sub + 8];
            float res = 0.f;
            #pragma unroll
            for (int l = 0; l < NL; l++) {
                float4 e0 = ev4[l * (ND / 4) + sub];
                float4 e1 = ev4[l * (ND / 4) + 8 + sub];
                float s = v0.x * e0.x + v0.y * e0.y + v0.z * e0.z + v0.w * e0.w
                        + v1.x * e1.x + v1.y * e1.y + v1.z * e1.z + v1.w * e1.w;
                s += __shfl_xor_sync(0xffffffffu, s, 1);
                s += __shfl_xor_sync(0xffffffffu, s, 2);
                s += __shfl_xor_sync(0xffffffffu, s, 4);
                if (sub == l) res = s;
            }
            if (sub < NL) g_dot[((size_t)b * NE + e) * NL + sub] = res;
        }
    }
    __syncthreads();              // s_is64 + recip visible; g_dot writes issued

    // release: publishes our g_dot writes cluster-wide. Non-blocking.
    asm volatile("barrier.cluster.arrive.aligned;" ::: "memory");

    // --- Phase A (inside arrive->wait window): stage paths, compacted ---
    const bool is64 = (s_is64 != 0);
    if (is64) {
        const int4* psrc = reinterpret_cast<const int4*>(
            (const unsigned char*)paths + ((size_t)b * NP + rank * PBLK) * NL * 8);
        int2* pdst = reinterpret_cast<int2*>(sp);
        #pragma unroll
        for (int i = tid; i < PBLK * NL / 2; i += ETH) {   // 5120 int4
            int4 v = __ldg(psrc + i);
            pdst[i] = make_int2(v.x, v.z);
        }
    } else {
        const int4* psrc = reinterpret_cast<const int4*>(
            (const unsigned char*)paths + ((size_t)b * NP + rank * PBLK) * NL * 4);
        int4* pdst = reinterpret_cast<int4*>(sp);
        #pragma unroll
        for (int i = tid; i < PBLK * NL / 4; i += ETH)     // 2560 int4
            pdst[i] = __ldg(psrc + i);
    }

    // acquire: all peers' g_dot slices now visible (L1 invalidated).
    asm volatile("barrier.cluster.wait.aligned;"   ::: "memory");

    // --- Phase B2: pull the full batch table from L2 into local smem ---
    {
        const float4* src4 = reinterpret_cast<const float4*>(g_dot + (size_t)b * NE * NL);
        float4* dst4 = reinterpret_cast<float4*>(tab);
        #pragma unroll
        for (int i = tid; i < (NE * NL) / 4; i += ETH)     // 2560 float4
            dst4[i] = src4[i];
    }
    __syncthreads();   // covers tab AND the Phase-A path staging

    // --- Phase C: local gather + reduce + coalesced store ---
    #pragma unroll
    for (int it = 0; it < EPPT; it++) {
        const int lp = it * ETH + tid;          // local p in [0, PBLK)
        const int* q = sp + lp * NL;
        float acc = 0.f;
        int cnt = 0;
        #pragma unroll
        for (int l = 0; l < NL; l++) {
            int idx = q[l];
            if (idx >= 0) { acc += tab[idx * NL + l]; cnt++; }
        }
        out[(size_t)b * NP + rank * PBLK + lp] = acc * recip[cnt];
    }
}

// ---------------------------------------------------------------------------
extern "C" void kernel_launch(void* const* d_in, const int* in_sizes, int n_in,
                              void* d_out, int out_size) {
    const float* emb   = (const float*)d_in[0];  // (B, E, D) float32
    const void*  paths = d_in[1];                // (B, P, L) int64 or int32
    const float* ev    = (const float*)d_in[2];  // (L, D) float32
    float* out = (float*)d_out;                  // (B, P) float32

    cudaFuncSetAttribute(fused_kernel, cudaFuncAttributeMaxDynamicSharedMemorySize,
                         FUSED_SMEM);
    dim3 grid(CSZ, NB);                          // (8, 16) = 128 CTAs, 16 clusters
    fused_kernel<<<grid, ETH, FUSED_SMEM>>>(emb, paths, ev, out);
}

// round 16
// speedup vs baseline: 3.7221x; 1.1688x over previous
#include <cuda_runtime.h>
#include <cuda_bf16.h>
#include <cstdint>

#define NB 16
#define NE 2048
#define NP 16384
#define NL 5
#define ND 64

// Per-(b,e,l) dot products, 16*2048*5 floats = 640 KB (L2-resident)
__device__ __align__(16) float g_dot[NB * NE * NL];
__device__ int g_is64;

// ---------------------------------------------------------------------------
// Kernel 1: dot[b,e,l] = sum_d emb[b,e,d] * ev[l,d]
// 8 lanes per row (2x float4 per lane, fully coalesced); 4 rows per warp.
// Per l: 8 FMAs then 3-step butterfly over the 8-lane group. (proven shape)
// Block 0 also sniffs the paths dtype (int64 -> odd 32-bit words are 0/-1).
// ---------------------------------------------------------------------------
__global__ __launch_bounds__(256) void dot_kernel(
    const float* __restrict__ emb, const float* __restrict__ ev,
    const int* __restrict__ pathw) {

    if (blockIdx.x == 0) {
        int bad = 0;
        #pragma unroll 4
        for (int i = threadIdx.x; i < 4096; i += 256) {
            int w = __ldg(pathw + 2 * i + 1);
            bad |= (w != 0 && w != -1);
        }
        bad = __syncthreads_or(bad);
        if (threadIdx.x == 0) g_is64 = bad ? 0 : 1;
    }

    int warp = threadIdx.x >> 5;
    int lane = threadIdx.x & 31;
    int grp  = lane >> 3;          // 4 rows per warp
    int sub  = lane & 7;           // 8 lanes per row
    int row  = blockIdx.x * 32 + warp * 4 + grp;   // (b*E + e)

    const float4* rp = reinterpret_cast<const float4*>(emb) + (size_t)row * (ND / 4);
    float4 v0 = rp[sub];
    float4 v1 = rp[sub + 8];

    const float4* ev4 = reinterpret_cast<const float4*>(ev);
    float res = 0.f;
    #pragma unroll
    for (int l = 0; l < NL; l++) {
        float4 e0 = ev4[l * (ND / 4) + sub];
        float4 e1 = ev4[l * (ND / 4) + 8 + sub];
        float s = v0.x * e0.x + v0.y * e0.y + v0.z * e0.z + v0.w * e0.w
                + v1.x * e1.x + v1.y * e1.y + v1.z * e1.z + v1.w * e1.w;
        s += __shfl_xor_sync(0xffffffffu, s, 1);
        s += __shfl_xor_sync(0xffffffffu, s, 2);
        s += __shfl_xor_sync(0xffffffffu, s, 4);
        if (sub == l) res = s;
    }
    if (sub < NL) g_dot[row * NL + sub] = res;
}

// ---------------------------------------------------------------------------
// Kernel 2 (v2): enc[b,p] = (sum_l valid ? dot[b, idx, l] : 0) * recip[cnt]
// NO shared memory, NO barrier. The 40 KB per-batch dot table is L1-cached
// (__ldg gathers; table << 228 KB L1). Path words read coalesced straight to
// registers (low 32-bit word works for int64 and int32: low word of -1 is
// -1; valid ids < 2^31). 256 blocks x 256 threads x 4 paths/thread:
// 20 independent loads + 20 independent gathers per thread, pure streaming.
// ---------------------------------------------------------------------------
#define ETH 256
#define EPPT 4
#define PBLK (ETH * EPPT)     // 1024 paths per block -> grid (16,16)

__constant__ float c_recip[8] = {
    0.f,                       // cnt=0: acc is 0; 0 matches 0/(0+eps)
    1.0f / (1.0f + 1e-9f),
    1.0f / (2.0f + 1e-9f),
    1.0f / (3.0f + 1e-9f),
    1.0f / (4.0f + 1e-9f),
    1.0f / (5.0f + 1e-9f),
    0.f, 0.f
};

__global__ __launch_bounds__(ETH) void enc_kernel(
    const void* __restrict__ paths, float* __restrict__ out) {

    const int b  = blockIdx.y;
    const int p0 = blockIdx.x * PBLK;
    const bool is64 = (g_is64 != 0);
    const float* tab = g_dot + (size_t)b * NE * NL;

    // Phase A: all 20 path words into registers (independent LDGs).
    int w[EPPT][NL];
    if (is64) {
        const int2* src = reinterpret_cast<const int2*>(
            (const unsigned char*)paths + ((size_t)b * NP + p0) * NL * 8);
        #pragma unroll
        for (int it = 0; it < EPPT; it++) {
            const int2* q = src + (it * ETH + threadIdx.x) * NL;
            #pragma unroll
            for (int l = 0; l < NL; l++) w[it][l] = __ldg(q + l).x;
        }
    } else {
        const int* src = reinterpret_cast<const int*>(paths)
                       + ((size_t)b * NP + p0) * NL;
        #pragma unroll
        for (int it = 0; it < EPPT; it++) {
            const int* q = src + (it * ETH + threadIdx.x) * NL;
            #pragma unroll
            for (int l = 0; l < NL; l++) w[it][l] = __ldg(q + l);
        }
    }

    // Phase B: 20 independent L1-cached gathers, then reduce + store.
    float acc[EPPT];
    int   cnt[EPPT];
    #pragma unroll
    for (int it = 0; it < EPPT; it++) { acc[it] = 0.f; cnt[it] = 0; }

    #pragma unroll
    for (int it = 0; it < EPPT; it++) {
        #pragma unroll
        for (int l = 0; l < NL; l++) {
            const int idx = w[it][l];
            if (idx >= 0) {
                acc[it] += __ldg(tab + idx * NL + l);
                cnt[it]++;
            }
        }
    }

    #pragma unroll
    for (int it = 0; it < EPPT; it++)
        out[(size_t)b * NP + p0 + it * ETH + threadIdx.x] = acc[it] * c_recip[cnt[it]];
}

// ---------------------------------------------------------------------------
extern "C" void kernel_launch(void* const* d_in, const int* in_sizes, int n_in,
                              void* d_out, int out_size) {
    const float* emb   = (const float*)d_in[0];  // (B, E, D) float32
    const void*  paths = d_in[1];                // (B, P, L) int64 or int32
    const float* ev    = (const float*)d_in[2];  // (L, D) float32
    float* out = (float*)d_out;                  // (B, P) float32

    // 32768 rows, 32 rows/block
    dot_kernel<<<NB * NE / 32, 256>>>(emb, ev, (const int*)paths);

    dim3 grid(NP / PBLK, NB);                    // (16, 16) = 256 blocks
    enc_kernel<<<grid, ETH>>>(paths, out);
}